// round 1
// baseline (speedup 1.0000x reference)
#include <cuda_runtime.h>
#include <cuda_bf16.h>
#include <math.h>

#define HIDDEN 768
#define BATCH 32
#define SEQ 512
#define NCHUNK 128
#define LC 8
#define LN_EPS 1e-12f

// ---- device scratch (no allocations allowed) ----
__device__ float g_scores[BATCH * SEQ];   // per-token attention logits
__device__ int   g_start[BATCH * NCHUNK];
__device__ int   g_len[BATCH * NCHUNK];
__device__ int   g_T[BATCH];              // rows needing scores per batch
__device__ float g_s0;                    // score of an all-zero (invalid) row

// ============================================================
// Kernel A: prefix sums, zero scores, s0
// grid = 32 blocks (one per batch), 128 threads
// ============================================================
__global__ void prep_kernel(const int* __restrict__ chunk_lens,
                            const float* __restrict__ dense_b,
                            const float* __restrict__ attn_bias,
                            const float* __restrict__ query) {
    int b = blockIdx.x;
    int c = threadIdx.x;
    int len = chunk_lens[b * NCHUNK + c];

    __shared__ int sc[NCHUNK];
    sc[c] = len;
    __syncthreads();
    // Hillis-Steele inclusive scan
    for (int off = 1; off < NCHUNK; off <<= 1) {
        int v = (c >= off) ? sc[c - off] : 0;
        __syncthreads();
        sc[c] += v;
        __syncthreads();
    }
    int incl = sc[c];
    g_start[b * NCHUNK + c] = incl - len;           // raw cumsum per reference
    int le = len;
    if (le < 0) le = 0;
    if (le > LC) le = LC;
    g_len[b * NCHUNK + c] = le;
    if (c == NCHUNK - 1) {
        int T = incl;
        if (T > SEQ) T = SEQ;
        if (T < 0) T = 0;
        g_T[b] = T;
    }
    // zero the score buffer for this batch
    for (int t = c; t < SEQ; t += NCHUNK) g_scores[b * SEQ + t] = 0.0f;

    if (b == 0) {
        float acc = 0.0f;
        for (int e = c; e < HIDDEN; e += NCHUNK)
            acc += query[e] * tanhf(dense_b[e] + attn_bias[e]);
        __shared__ float red[NCHUNK];
        red[c] = acc;
        __syncthreads();
        for (int off = 64; off > 0; off >>= 1) {
            if (c < off) red[c] += red[c + off];
            __syncthreads();
        }
        if (c == 0) g_s0 = red[0];
    }
}

// ============================================================
// Kernel B: scores[b,t] = sum_e q[e]*tanh( sum_d W[e,d]*X[b,t,d] + bb[e] )
// fp32 tiled GEMM with fused epilogue. BM=64, BN=64, BK=16, 256 thr, 4x4 micro.
// grid = (12 N-tiles, 8 row-tiles, 32 batches)
// ============================================================
#define BM 64
#define BN 64
#define BK 16

__global__ void __launch_bounds__(256, 4)
gemm_scores_kernel(const float* __restrict__ tokens,
                   const float* __restrict__ W,
                   const float* __restrict__ dense_b,
                   const float* __restrict__ attn_bias,
                   const float* __restrict__ query) {
    int b = blockIdx.z;
    int Tb = g_T[b];
    int row0 = blockIdx.y * BM;
    if (row0 >= Tb) return;
    int e0 = blockIdx.x * BN;

    const float* X = tokens + (size_t)b * SEQ * HIDDEN;

    __shared__ float As[BM][BK + 4];   // row stride 20 floats (16B aligned rows)
    __shared__ float Bs[BK][BN + 4];   // row stride 68 floats (16B aligned rows)
    __shared__ float srow[BM];

    int tid = threadIdx.x;
    int tx = tid & 15;       // 0..15 -> 4 e-cols each
    int ty = tid >> 4;       // 0..15 -> 4 rows each

    // loader mapping: each thread loads one float4 per tile for As and Bs
    int lr = tid >> 2;            // 0..63
    int lj = (tid & 3) << 2;      // 0,4,8,12
    int rowIdx = row0 + lr;
    bool rvalid = (rowIdx < Tb);
    const float4* Xrow = (const float4*)(X + (size_t)(rvalid ? rowIdx : 0) * HIDDEN);
    const float4* Wrow = (const float4*)(W + (size_t)(e0 + lr) * HIDDEN);

    float acc[4][4] = {};

    for (int k0 = 0; k0 < HIDDEN; k0 += BK) {
        float4 av = rvalid ? Xrow[(k0 + lj) >> 2] : make_float4(0.f, 0.f, 0.f, 0.f);
        *(float4*)&As[lr][lj] = av;
        float4 bv = Wrow[(k0 + lj) >> 2];
        Bs[lj + 0][lr] = bv.x;
        Bs[lj + 1][lr] = bv.y;
        Bs[lj + 2][lr] = bv.z;
        Bs[lj + 3][lr] = bv.w;
        __syncthreads();

        #pragma unroll
        for (int j = 0; j < BK; j++) {
            float a0 = As[ty * 4 + 0][j];
            float a1 = As[ty * 4 + 1][j];
            float a2 = As[ty * 4 + 2][j];
            float a3 = As[ty * 4 + 3][j];
            float4 b4 = *(const float4*)&Bs[j][tx * 4];
            acc[0][0] += a0 * b4.x; acc[0][1] += a0 * b4.y; acc[0][2] += a0 * b4.z; acc[0][3] += a0 * b4.w;
            acc[1][0] += a1 * b4.x; acc[1][1] += a1 * b4.y; acc[1][2] += a1 * b4.z; acc[1][3] += a1 * b4.w;
            acc[2][0] += a2 * b4.x; acc[2][1] += a2 * b4.y; acc[2][2] += a2 * b4.z; acc[2][3] += a2 * b4.w;
            acc[3][0] += a3 * b4.x; acc[3][1] += a3 * b4.y; acc[3][2] += a3 * b4.z; acc[3][3] += a3 * b4.w;
        }
        __syncthreads();
    }

    // epilogue: p[row] = sum_n q[e]*tanh(acc + bb[e]); reduce across tx; atomic to global
    if (tid < BM) srow[tid] = 0.0f;
    __syncthreads();

    float qv[4], bbv[4];
    #pragma unroll
    for (int n = 0; n < 4; n++) {
        int e = e0 + tx * 4 + n;
        qv[n]  = query[e];
        bbv[n] = dense_b[e] + attn_bias[e];
    }
    #pragma unroll
    for (int m = 0; m < 4; m++) {
        float p = 0.0f;
        #pragma unroll
        for (int n = 0; n < 4; n++)
            p += qv[n] * tanhf(acc[m][n] + bbv[n]);
        atomicAdd(&srow[ty * 4 + m], p);
    }
    __syncthreads();
    if (tid < BM) {
        int r = row0 + tid;
        if (r < Tb) atomicAdd(&g_scores[b * SEQ + r], srow[tid]);
    }
}

// ============================================================
// Kernel C: per-chunk softmax + weighted sum + LayerNorm
// grid = 4096 blocks (one per (b,c)), 256 threads (3 dims each)
// ============================================================
__device__ __forceinline__ float block_reduce_sum(float val, float* sred) {
    #pragma unroll
    for (int off = 16; off > 0; off >>= 1)
        val += __shfl_down_sync(0xffffffffu, val, off);
    int warp = threadIdx.x >> 5, lane = threadIdx.x & 31;
    if (lane == 0) sred[warp] = val;
    __syncthreads();
    if (threadIdx.x < 8) {
        float v = sred[threadIdx.x];
        #pragma unroll
        for (int off = 4; off > 0; off >>= 1)
            v += __shfl_down_sync(0xffu, v, off);
        if (threadIdx.x == 0) sred[0] = v;
    }
    __syncthreads();
    float r = sred[0];
    __syncthreads();
    return r;
}

__global__ void __launch_bounds__(256)
chunk_embed_kernel(const float* __restrict__ tokens,
                   const float* __restrict__ ln_w,
                   const float* __restrict__ ln_b,
                   float* __restrict__ out_chunk) {
    int bc = blockIdx.x;
    int b = bc >> 7;
    int len = g_len[bc];
    int start = g_start[bc];
    float s0 = g_s0;

    // softmax over the 8 slots (invalid slots carry s0) — redundant per thread, cheap
    float sc[LC];
    #pragma unroll
    for (int j = 0; j < LC; j++) {
        if (j < len) {
            int t = start + j;
            if (t > SEQ - 1) t = SEQ - 1;
            if (t < 0) t = 0;
            sc[j] = g_scores[b * SEQ + t];
        } else {
            sc[j] = s0;
        }
    }
    float m = sc[0];
    #pragma unroll
    for (int j = 1; j < LC; j++) m = fmaxf(m, sc[j]);
    float den = 0.0f;
    float w8[LC];
    #pragma unroll
    for (int j = 0; j < LC; j++) { w8[j] = expf(sc[j] - m); den += w8[j]; }
    float inv_den = 1.0f / den;

    int tid = threadIdx.x;
    __shared__ float sred[8];

    // weighted sum of valid token rows (invalid rows are zero in the reference gather)
    float v[3];
    #pragma unroll
    for (int i = 0; i < 3; i++) {
        int d = tid + i * 256;
        float acc = 0.0f;
        #pragma unroll
        for (int j = 0; j < LC; j++) {
            if (j < len) {
                int t = start + j;
                if (t > SEQ - 1) t = SEQ - 1;
                if (t < 0) t = 0;
                acc += (w8[j] * inv_den) * tokens[((size_t)b * SEQ + t) * HIDDEN + d];
            }
        }
        v[i] = acc;
    }

    float total = block_reduce_sum(v[0] + v[1] + v[2], sred);
    float u = total * (1.0f / HIDDEN);
    float d0 = v[0] - u, d1 = v[1] - u, d2 = v[2] - u;
    float ssq = block_reduce_sum(d0 * d0 + d1 * d1 + d2 * d2, sred);
    float var = ssq * (1.0f / HIDDEN);
    float inv = rsqrtf(var + LN_EPS);

    float* outp = out_chunk + (size_t)bc * HIDDEN;
    outp[tid]       = ln_w[tid]       * (d0 * inv) + ln_b[tid];
    outp[tid + 256] = ln_w[tid + 256] * (d1 * inv) + ln_b[tid + 256];
    outp[tid + 512] = ln_w[tid + 512] * (d2 * inv) + ln_b[tid + 512];
}

// ============================================================
// Kernel D: sentence_embedding = max over 128 chunks
// grid = (3, 32), 256 threads
// ============================================================
__global__ void __launch_bounds__(256)
sent_max_kernel(const float* __restrict__ chunk_feat, float* __restrict__ out) {
    int b = blockIdx.y;
    int d = blockIdx.x * 256 + threadIdx.x;
    const float* p = chunk_feat + (size_t)b * NCHUNK * HIDDEN + d;
    float m = p[0];
    #pragma unroll 8
    for (int c = 1; c < NCHUNK; c++) m = fmaxf(m, p[(size_t)c * HIDDEN]);
    out[b * HIDDEN + d] = m;
}

// ============================================================
extern "C" void kernel_launch(void* const* d_in, const int* in_sizes, int n_in,
                              void* d_out, int out_size) {
    const float* tokens    = (const float*)d_in[0];
    const int*   chunk_lens= (const int*)d_in[1];
    const float* dense_w   = (const float*)d_in[2];
    const float* dense_b   = (const float*)d_in[3];
    const float* attn_bias = (const float*)d_in[4];
    const float* query     = (const float*)d_in[5];
    const float* ln_w      = (const float*)d_in[6];
    const float* ln_b      = (const float*)d_in[7];
    float* out = (float*)d_out;

    float* out_chunk = out;                                     // [32,128,768]
    float* out_sent  = out + (size_t)BATCH * NCHUNK * HIDDEN;   // [32,768]

    prep_kernel<<<BATCH, NCHUNK>>>(chunk_lens, dense_b, attn_bias, query);

    dim3 gB(HIDDEN / BN, SEQ / BM, BATCH);  // (12, 8, 32); row-tiles early-exit on T_b
    gemm_scores_kernel<<<gB, 256>>>(tokens, dense_w, dense_b, attn_bias, query);

    chunk_embed_kernel<<<BATCH * NCHUNK, 256>>>(tokens, ln_w, ln_b, out_chunk);

    dim3 gD(HIDDEN / 256, BATCH);
    sent_max_kernel<<<gD, 256>>>(out_chunk, out_sent);
}

// round 4
// speedup vs baseline: 2.1768x; 2.1768x over previous
#include <cuda_runtime.h>
#include <cuda_fp16.h>
#include <math.h>
#include <stdint.h>

#define HIDDEN 768
#define BATCH 32
#define SEQ 512
#define NCHUNK 128
#define LC 8
#define LN_EPS 1e-12f

// GEMM tiling
#define BM 64
#define BN 64
#define BK 32
#define NCH (HIDDEN / BK)      // 24 k-chunks
#define MAXT 384               // max rows per batch (128 chunks * len<=3)
#define LDT 40                 // smem row stride in fp16 elems (80B)

// ---- device scratch ----
__device__ float g_scores[BATCH * SEQ];
__device__ int   g_start[BATCH * NCHUNK];
__device__ int   g_len[BATCH * NCHUNK];
__device__ int   g_T[BATCH];
__device__ float g_s0;
__device__ float g_pmax[8 * BATCH * HIDDEN];

__device__ __forceinline__ uint32_t smem_u32(const void* p) {
    uint32_t a;
    asm("{ .reg .u64 t; cvta.to.shared.u64 t, %1; cvt.u32.u64 %0, t; }" : "=r"(a) : "l"(p));
    return a;
}

__device__ __forceinline__ uint32_t h2_as_u32(__half2 h) {
    union { __half2 h; uint32_t u; } cvt;
    cvt.h = h;
    return cvt.u;
}

#define LDSM_X4(r, addr) \
    asm volatile("ldmatrix.sync.aligned.m8n8.x4.shared.b16 {%0,%1,%2,%3}, [%4];" \
        : "=r"((r)[0]), "=r"((r)[1]), "=r"((r)[2]), "=r"((r)[3]) : "r"(addr))

#define LDSM_X2(r, addr) \
    asm volatile("ldmatrix.sync.aligned.m8n8.x2.shared.b16 {%0,%1}, [%2];" \
        : "=r"((r)[0]), "=r"((r)[1]) : "r"(addr))

#define MMA16816(d, a, bf) \
    asm volatile("mma.sync.aligned.m16n8k16.row.col.f32.f16.f16.f32 " \
        "{%0,%1,%2,%3}, {%4,%5,%6,%7}, {%8,%9}, {%0,%1,%2,%3};" \
        : "+f"((d)[0]), "+f"((d)[1]), "+f"((d)[2]), "+f"((d)[3]) \
        : "r"((a)[0]), "r"((a)[1]), "r"((a)[2]), "r"((a)[3]), \
          "r"((bf)[0]), "r"((bf)[1]))

// split float4 into fp16 hi and lo (x - hi) packed as uint2 each
__device__ __forceinline__ void split_pack(float4 v, uint2& hi, uint2& lo) {
    __half2 h01 = __floats2half2_rn(v.x, v.y);
    __half2 h23 = __floats2half2_rn(v.z, v.w);
    float2 f01 = __half22float2(h01);
    float2 f23 = __half22float2(h23);
    __half2 l01 = __floats2half2_rn(v.x - f01.x, v.y - f01.y);
    __half2 l23 = __floats2half2_rn(v.z - f23.x, v.w - f23.y);
    hi.x = h2_as_u32(h01); hi.y = h2_as_u32(h23);
    lo.x = h2_as_u32(l01); lo.y = h2_as_u32(l23);
}

// ============================================================
// Kernel A: prefix sums, zero scores, s0
// ============================================================
__global__ void prep_kernel(const int* __restrict__ chunk_lens,
                            const float* __restrict__ dense_b,
                            const float* __restrict__ attn_bias,
                            const float* __restrict__ query) {
    int b = blockIdx.x;
    int c = threadIdx.x;
    int len = chunk_lens[b * NCHUNK + c];

    __shared__ int sc[NCHUNK];
    sc[c] = len;
    __syncthreads();
    for (int off = 1; off < NCHUNK; off <<= 1) {
        int v = (c >= off) ? sc[c - off] : 0;
        __syncthreads();
        sc[c] += v;
        __syncthreads();
    }
    int incl = sc[c];
    g_start[b * NCHUNK + c] = incl - len;
    int le = len;
    if (le < 0) le = 0;
    if (le > LC) le = LC;
    g_len[b * NCHUNK + c] = le;
    if (c == NCHUNK - 1) {
        int T = incl;
        if (T > SEQ) T = SEQ;
        if (T < 0) T = 0;
        g_T[b] = T;
    }
    for (int t = c; t < SEQ; t += NCHUNK) g_scores[b * SEQ + t] = 0.0f;

    if (b == 0) {
        float acc = 0.0f;
        for (int e = c; e < HIDDEN; e += NCHUNK)
            acc += query[e] * tanhf(dense_b[e] + attn_bias[e]);
        __shared__ float red[NCHUNK];
        red[c] = acc;
        __syncthreads();
        for (int off = 64; off > 0; off >>= 1) {
            if (c < off) red[c] += red[c + off];
            __syncthreads();
        }
        if (c == 0) g_s0 = red[0];
    }
}

// ============================================================
// Kernel B: HMMA (mma.sync fp16-split) GEMM + fused tanh/q epilogue
// scores[b,t] = sum_e q[e]*tanh( sum_d W[e,d]*X[b,t,d] + bb[e] )
// grid = (12 n-tiles, 6 m-tiles, 32 batches), 128 threads (4 warps 2x2)
// ============================================================
__global__ void __launch_bounds__(128)
gemm_hmma_kernel(const float* __restrict__ tokens,
                 const float* __restrict__ W,
                 const float* __restrict__ dense_b,
                 const float* __restrict__ attn_bias,
                 const float* __restrict__ query) {
    int b = blockIdx.z;
    int Tb = g_T[b];
    int row0 = blockIdx.y * BM;
    if (row0 >= Tb) return;
    int e0 = blockIdx.x * BN;

    __shared__ __half sA[2][2][BM * LDT];   // [stage][hi/lo]
    __shared__ __half sB[2][2][BN * LDT];
    __shared__ float qs[BN], bbs[BN];

    int tid = threadIdx.x;
    int wid = tid >> 5;
    int lane = tid & 31;
    int warp_m = wid & 1;          // 2 m-warps
    int warp_n = wid >> 1;         // 2 n-warps

    if (tid < BN) {
        int e = e0 + tid;
        qs[tid]  = query[e];
        bbs[tid] = dense_b[e] + attn_bias[e];
    }

    // loader: pass p: row = p*16 + tid/8, col = (tid%8)*4
    int lrow = tid >> 3;
    int lcol = (tid & 7) << 2;
    const float* agp = tokens + (size_t)b * SEQ * HIDDEN + (size_t)(row0 + lrow) * HIDDEN + lcol;
    const float* bgp = W + (size_t)(e0 + lrow) * HIDDEN + lcol;

    float4 ra[4], rb[4];
    #define PREFETCH(s) do { \
        int k0_ = (s) * BK; \
        _Pragma("unroll") \
        for (int p = 0; p < 4; ++p) { \
            ra[p] = *(const float4*)(agp + (size_t)p * 16 * HIDDEN + k0_); \
            rb[p] = *(const float4*)(bgp + (size_t)p * 16 * HIDDEN + k0_); \
        } \
    } while (0)

    #define STOREBUF(st) do { \
        _Pragma("unroll") \
        for (int p = 0; p < 4; ++p) { \
            uint2 hi, lo; \
            int off = (p * 16 + lrow) * LDT + lcol; \
            split_pack(ra[p], hi, lo); \
            *(uint2*)&sA[st][0][off] = hi; \
            *(uint2*)&sA[st][1][off] = lo; \
            split_pack(rb[p], hi, lo); \
            *(uint2*)&sB[st][0][off] = hi; \
            *(uint2*)&sB[st][1][off] = lo; \
        } \
    } while (0)

    float acc[2][4][4] = {};

    // smem base addresses (uint32 shared space)
    uint32_t aHiB = smem_u32(&sA[0][0][0]);
    uint32_t stageA = smem_u32(&sA[1][0][0]) - aHiB;     // bytes per A stage
    uint32_t loA = smem_u32(&sA[0][1][0]) - aHiB;
    uint32_t bHiB = smem_u32(&sB[0][0][0]);
    uint32_t stageB = smem_u32(&sB[1][0][0]) - bHiB;
    uint32_t loB = smem_u32(&sB[0][1][0]) - bHiB;

    // per-warp ldmatrix offsets (in fp16 elems, converted to bytes)
    int aRow = warp_m * 32 + (lane & 15);      // + mt*16
    int aCol = (lane >> 4) * 8;                // + k16*16
    int bRow = warp_n * 32 + (lane & 7);       // + nt*8
    int bCol = ((lane >> 3) & 1) * 8;          // + k16*16

    PREFETCH(0);
    STOREBUF(0);
    __syncthreads();

    for (int s = 0; s < NCH; ++s) {
        int st = s & 1;
        if (s + 1 < NCH) PREFETCH(s + 1);

        uint32_t aB = aHiB + st * stageA;
        uint32_t bB = bHiB + st * stageB;

        #pragma unroll
        for (int k16 = 0; k16 < 2; ++k16) {
            uint32_t ahi[2][4], alo[2][4], bhi[4][2], blo[4][2];
            #pragma unroll
            for (int mt = 0; mt < 2; ++mt) {
                uint32_t ao = aB + ((aRow + mt * 16) * LDT + aCol + k16 * 16) * 2;
                LDSM_X4(ahi[mt], ao);
                LDSM_X4(alo[mt], ao + loA);
            }
            #pragma unroll
            for (int nt = 0; nt < 4; ++nt) {
                uint32_t bo = bB + ((bRow + nt * 8) * LDT + bCol + k16 * 16) * 2;
                LDSM_X2(bhi[nt], bo);
                LDSM_X2(blo[nt], bo + loB);
            }
            #pragma unroll
            for (int mt = 0; mt < 2; ++mt)
                #pragma unroll
                for (int nt = 0; nt < 4; ++nt) {
                    MMA16816(acc[mt][nt], ahi[mt], bhi[nt]);
                    MMA16816(acc[mt][nt], ahi[mt], blo[nt]);
                    MMA16816(acc[mt][nt], alo[mt], bhi[nt]);
                }
        }

        if (s + 1 < NCH) {
            STOREBUF((s + 1) & 1);
            __syncthreads();
        }
    }

    // epilogue: p[row] += sum_n q[n] * tanh(acc + bb[n]); quad-reduce; atomic
    float part[2][2] = {};
    #pragma unroll
    for (int mt = 0; mt < 2; ++mt)
        #pragma unroll
        for (int nt = 0; nt < 4; ++nt) {
            int nl = warp_n * 32 + nt * 8 + (lane & 3) * 2;
            float q0 = qs[nl], q1 = qs[nl + 1];
            float b0 = bbs[nl], b1 = bbs[nl + 1];
            part[mt][0] += q0 * tanhf(acc[mt][nt][0] + b0)
                         + q1 * tanhf(acc[mt][nt][1] + b1);
            part[mt][1] += q0 * tanhf(acc[mt][nt][2] + b0)
                         + q1 * tanhf(acc[mt][nt][3] + b1);
        }
    #pragma unroll
    for (int mt = 0; mt < 2; ++mt)
        #pragma unroll
        for (int i = 0; i < 2; ++i) {
            part[mt][i] += __shfl_xor_sync(0xffffffffu, part[mt][i], 1);
            part[mt][i] += __shfl_xor_sync(0xffffffffu, part[mt][i], 2);
        }
    if ((lane & 3) == 0) {
        #pragma unroll
        for (int mt = 0; mt < 2; ++mt)
            #pragma unroll
            for (int i = 0; i < 2; ++i) {
                int r = row0 + warp_m * 32 + mt * 16 + i * 8 + (lane >> 2);
                if (r < Tb) atomicAdd(&g_scores[b * SEQ + r], part[mt][i]);
            }
    }
}

// ============================================================
// Kernel C: per-chunk softmax + weighted sum + LayerNorm
// ============================================================
__device__ __forceinline__ float block_reduce_sum(float val, float* sred) {
    #pragma unroll
    for (int off = 16; off > 0; off >>= 1)
        val += __shfl_down_sync(0xffffffffu, val, off);
    int warp = threadIdx.x >> 5, lane = threadIdx.x & 31;
    if (lane == 0) sred[warp] = val;
    __syncthreads();
    if (threadIdx.x < 8) {
        float v = sred[threadIdx.x];
        #pragma unroll
        for (int off = 4; off > 0; off >>= 1)
            v += __shfl_down_sync(0xffu, v, off);
        if (threadIdx.x == 0) sred[0] = v;
    }
    __syncthreads();
    float r = sred[0];
    __syncthreads();
    return r;
}

__global__ void __launch_bounds__(256)
chunk_embed_kernel(const float* __restrict__ tokens,
                   const float* __restrict__ ln_w,
                   const float* __restrict__ ln_b,
                   float* __restrict__ out_chunk) {
    int bc = blockIdx.x;
    int b = bc >> 7;
    int len = g_len[bc];
    int start = g_start[bc];
    float s0 = g_s0;

    float sc[LC];
    #pragma unroll
    for (int j = 0; j < LC; j++) {
        if (j < len) {
            int t = start + j;
            if (t > SEQ - 1) t = SEQ - 1;
            if (t < 0) t = 0;
            sc[j] = g_scores[b * SEQ + t];
        } else {
            sc[j] = s0;
        }
    }
    float m = sc[0];
    #pragma unroll
    for (int j = 1; j < LC; j++) m = fmaxf(m, sc[j]);
    float den = 0.0f;
    float w8[LC];
    #pragma unroll
    for (int j = 0; j < LC; j++) { w8[j] = expf(sc[j] - m); den += w8[j]; }
    float inv_den = 1.0f / den;

    int tid = threadIdx.x;
    __shared__ float sred[8];

    float v[3];
    #pragma unroll
    for (int i = 0; i < 3; i++) {
        int d = tid + i * 256;
        float acc = 0.0f;
        #pragma unroll
        for (int j = 0; j < LC; j++) {
            if (j < len) {
                int t = start + j;
                if (t > SEQ - 1) t = SEQ - 1;
                if (t < 0) t = 0;
                acc += (w8[j] * inv_den) * tokens[((size_t)b * SEQ + t) * HIDDEN + d];
            }
        }
        v[i] = acc;
    }

    float total = block_reduce_sum(v[0] + v[1] + v[2], sred);
    float u = total * (1.0f / HIDDEN);
    float d0 = v[0] - u, d1 = v[1] - u, d2 = v[2] - u;
    float ssq = block_reduce_sum(d0 * d0 + d1 * d1 + d2 * d2, sred);
    float var = ssq * (1.0f / HIDDEN);
    float inv = rsqrtf(var + LN_EPS);

    float* outp = out_chunk + (size_t)bc * HIDDEN;
    outp[tid]       = ln_w[tid]       * (d0 * inv) + ln_b[tid];
    outp[tid + 256] = ln_w[tid + 256] * (d1 * inv) + ln_b[tid + 256];
    outp[tid + 512] = ln_w[tid + 512] * (d2 * inv) + ln_b[tid + 512];
}

// ============================================================
// Kernel D: sentence max, 2-stage
// ============================================================
__global__ void __launch_bounds__(256)
sent_partial_kernel(const float* __restrict__ chunk_feat) {
    int b = blockIdx.y;
    int g = blockIdx.z;
    int d = blockIdx.x * 256 + threadIdx.x;
    const float* p = chunk_feat + ((size_t)b * NCHUNK + g * 16) * HIDDEN + d;
    float m0 = p[0], m1 = p[HIDDEN];
    #pragma unroll
    for (int c = 2; c < 16; c += 2) {
        m0 = fmaxf(m0, p[(size_t)c * HIDDEN]);
        m1 = fmaxf(m1, p[(size_t)(c + 1) * HIDDEN]);
    }
    g_pmax[((size_t)g * BATCH + b) * HIDDEN + d] = fmaxf(m0, m1);
}

__global__ void __launch_bounds__(256)
sent_final_kernel(float* __restrict__ out) {
    int b = blockIdx.y;
    int d = blockIdx.x * 256 + threadIdx.x;
    float m = g_pmax[(size_t)b * HIDDEN + d];
    #pragma unroll
    for (int g = 1; g < 8; g++)
        m = fmaxf(m, g_pmax[((size_t)g * BATCH + b) * HIDDEN + d]);
    out[b * HIDDEN + d] = m;
}

// ============================================================
extern "C" void kernel_launch(void* const* d_in, const int* in_sizes, int n_in,
                              void* d_out, int out_size) {
    const float* tokens    = (const float*)d_in[0];
    const int*   chunk_lens= (const int*)d_in[1];
    const float* dense_w   = (const float*)d_in[2];
    const float* dense_b   = (const float*)d_in[3];
    const float* attn_bias = (const float*)d_in[4];
    const float* query     = (const float*)d_in[5];
    const float* ln_w      = (const float*)d_in[6];
    const float* ln_b      = (const float*)d_in[7];
    float* out = (float*)d_out;

    float* out_chunk = out;
    float* out_sent  = out + (size_t)BATCH * NCHUNK * HIDDEN;

    prep_kernel<<<BATCH, NCHUNK>>>(chunk_lens, dense_b, attn_bias, query);

    dim3 gB(HIDDEN / BN, MAXT / BM, BATCH);   // (12, 6, 32), early exit on T_b
    gemm_hmma_kernel<<<gB, 128>>>(tokens, dense_w, dense_b, attn_bias, query);

    chunk_embed_kernel<<<BATCH * NCHUNK, 256>>>(tokens, ln_w, ln_b, out_chunk);

    dim3 gP(HIDDEN / 256, BATCH, 8);
    sent_partial_kernel<<<gP, 256>>>(out_chunk);
    dim3 gF(HIDDEN / 256, BATCH);
    sent_final_kernel<<<gF, 256>>>(out_sent);
}

// round 5
// speedup vs baseline: 2.3549x; 1.0818x over previous
#include <cuda_runtime.h>
#include <cuda_fp16.h>
#include <math.h>
#include <stdint.h>

#define HIDDEN 768
#define BATCH 32
#define SEQ 512
#define NCHUNK 128
#define LC 8
#define LN_EPS 1e-12f
#define MAXT 384

// GEMM tiling
#define BM 64
#define BN 128
#define BK 32
#define NCH (HIDDEN / BK)   // 24
#define LDT 40              // smem row stride in halves (80B)

// ---- device scratch ----
__device__ float g_scores[BATCH * SEQ];
__device__ int   g_start[BATCH * NCHUNK];
__device__ int   g_len[BATCH * NCHUNK];
__device__ int   g_T[BATCH];
__device__ float g_s0;
__device__ float g_pmax[8 * BATCH * HIDDEN];
__device__ __half g_Xhi[BATCH * MAXT * HIDDEN];
__device__ __half g_Xlo[BATCH * MAXT * HIDDEN];
__device__ __half g_Whi[HIDDEN * HIDDEN];
__device__ __half g_Wlo[HIDDEN * HIDDEN];

__device__ __forceinline__ uint32_t smem_u32(const void* p) {
    uint32_t a;
    asm("{ .reg .u64 t; cvta.to.shared.u64 t, %1; cvt.u32.u64 %0, t; }" : "=r"(a) : "l"(p));
    return a;
}

__device__ __forceinline__ uint32_t h2_as_u32(__half2 h) {
    union { __half2 h; uint32_t u; } cvt;
    cvt.h = h;
    return cvt.u;
}

#define LDSM_X4(r, addr) \
    asm volatile("ldmatrix.sync.aligned.m8n8.x4.shared.b16 {%0,%1,%2,%3}, [%4];" \
        : "=r"((r)[0]), "=r"((r)[1]), "=r"((r)[2]), "=r"((r)[3]) : "r"(addr))

#define LDSM_X2(r, addr) \
    asm volatile("ldmatrix.sync.aligned.m8n8.x2.shared.b16 {%0,%1}, [%2];" \
        : "=r"((r)[0]), "=r"((r)[1]) : "r"(addr))

#define MMA16816(d, a, bf) \
    asm volatile("mma.sync.aligned.m16n8k16.row.col.f32.f16.f16.f32 " \
        "{%0,%1,%2,%3}, {%4,%5,%6,%7}, {%8,%9}, {%0,%1,%2,%3};" \
        : "+f"((d)[0]), "+f"((d)[1]), "+f"((d)[2]), "+f"((d)[3]) \
        : "r"((a)[0]), "r"((a)[1]), "r"((a)[2]), "r"((a)[3]), \
          "r"((bf)[0]), "r"((bf)[1]))

#define CP_ASYNC16(dst, src) \
    asm volatile("cp.async.cg.shared.global [%0], [%1], 16;" :: "r"(dst), "l"(src))
#define CP_COMMIT() asm volatile("cp.async.commit_group;" ::: "memory")
#define CP_WAIT(n)  asm volatile("cp.async.wait_group %0;" :: "n"(n) : "memory")

__device__ __forceinline__ void split_pack(float4 v, uint2& hi, uint2& lo) {
    __half2 h01 = __floats2half2_rn(v.x, v.y);
    __half2 h23 = __floats2half2_rn(v.z, v.w);
    float2 f01 = __half22float2(h01);
    float2 f23 = __half22float2(h23);
    __half2 l01 = __floats2half2_rn(v.x - f01.x, v.y - f01.y);
    __half2 l23 = __floats2half2_rn(v.z - f23.x, v.w - f23.y);
    hi.x = h2_as_u32(h01); hi.y = h2_as_u32(h23);
    lo.x = h2_as_u32(l01); lo.y = h2_as_u32(l23);
}

// ============================================================
// Kernel A: prefix sums, zero scores, s0
// ============================================================
__global__ void prep_kernel(const int* __restrict__ chunk_lens,
                            const float* __restrict__ dense_b,
                            const float* __restrict__ attn_bias,
                            const float* __restrict__ query) {
    int b = blockIdx.x;
    int c = threadIdx.x;
    int len = chunk_lens[b * NCHUNK + c];

    __shared__ int sc[NCHUNK];
    sc[c] = len;
    __syncthreads();
    for (int off = 1; off < NCHUNK; off <<= 1) {
        int v = (c >= off) ? sc[c - off] : 0;
        __syncthreads();
        sc[c] += v;
        __syncthreads();
    }
    int incl = sc[c];
    g_start[b * NCHUNK + c] = incl - len;
    int le = len;
    if (le < 0) le = 0;
    if (le > LC) le = LC;
    g_len[b * NCHUNK + c] = le;
    if (c == NCHUNK - 1) {
        int T = incl;
        if (T > SEQ) T = SEQ;
        if (T < 0) T = 0;
        g_T[b] = T;
    }
    for (int t = c; t < SEQ; t += NCHUNK) g_scores[b * SEQ + t] = 0.0f;

    if (b == 0) {
        float acc = 0.0f;
        for (int e = c; e < HIDDEN; e += NCHUNK)
            acc += query[e] * tanhf(dense_b[e] + attn_bias[e]);
        __shared__ float red[NCHUNK];
        red[c] = acc;
        __syncthreads();
        for (int off = 64; off > 0; off >>= 1) {
            if (c < off) red[c] += red[c + off];
            __syncthreads();
        }
        if (c == 0) g_s0 = red[0];
    }
}

// ============================================================
// Kernel A2: fp32 -> fp16 hi/lo split for X (first MAXT rows/batch) and W
// grid.x: 0..767 => X blocks (b = blk/24, 16 rows each); 768..815 => W (16 rows)
// ============================================================
__global__ void __launch_bounds__(256)
convert_kernel(const float* __restrict__ tokens, const float* __restrict__ W) {
    int blk = blockIdx.x;
    int tid = threadIdx.x;
    if (blk < 768) {
        int b = blk / 24;
        int rg = blk - b * 24;
        int row0 = rg * 16;
        if (row0 >= g_T[b]) return;
        const float4* src = (const float4*)(tokens + ((size_t)b * SEQ + row0) * HIDDEN);
        size_t dst0 = ((size_t)b * MAXT + row0) * HIDDEN;
        #pragma unroll
        for (int i = 0; i < 12; ++i) {
            int idx = tid + i * 256;        // 0..3071 float4s (16 rows * 192)
            float4 v = src[idx];
            uint2 hi, lo;
            split_pack(v, hi, lo);
            *(uint2*)&g_Xhi[dst0 + (size_t)idx * 4] = hi;
            *(uint2*)&g_Xlo[dst0 + (size_t)idx * 4] = lo;
        }
    } else {
        int row0 = (blk - 768) * 16;
        const float4* src = (const float4*)(W + (size_t)row0 * HIDDEN);
        size_t dst0 = (size_t)row0 * HIDDEN;
        #pragma unroll
        for (int i = 0; i < 12; ++i) {
            int idx = tid + i * 256;
            float4 v = src[idx];
            uint2 hi, lo;
            split_pack(v, hi, lo);
            *(uint2*)&g_Whi[dst0 + (size_t)idx * 4] = hi;
            *(uint2*)&g_Wlo[dst0 + (size_t)idx * 4] = lo;
        }
    }
}

// ============================================================
// Kernel B: HMMA GEMM (pre-split operands) + fused tanh/q epilogue
// grid = (6 n-tiles, 6 m-tiles, 32 batches), 256 threads (8 warps 2m x 4n)
// dynamic smem: A 2st x 2(hi/lo) x 64x40 halves; B 2st x 2 x 128x40 halves
// ============================================================
#define A_ST_H   5120            // halves per A stage (2*64*40)
#define A_HL_H   2560
#define B_BASE_B 20480           // byte offset of B region
#define B_ST_H   10240
#define B_HL_H   5120
#define SMEM_GEMM 61440

__global__ void __launch_bounds__(256)
gemm_hmma_kernel(const float* __restrict__ dense_b,
                 const float* __restrict__ attn_bias,
                 const float* __restrict__ query) {
    int b = blockIdx.z;
    int Tb = g_T[b];
    int row0 = blockIdx.y * BM;
    if (row0 >= Tb) return;
    int e0 = blockIdx.x * BN;

    extern __shared__ char smem[];
    uint32_t S = smem_u32(smem);
    __shared__ float qs[BN], bbs[BN];

    int tid = threadIdx.x;
    int wid = tid >> 5;
    int lane = tid & 31;
    int warp_m = wid & 1;
    int warp_n = wid >> 1;          // 0..3

    if (tid < BN) {
        int e = e0 + tid;
        qs[tid]  = query[e];
        bbs[tid] = dense_b[e] + attn_bias[e];
    }

    // ---- cp.async stage loader: 1536 16B chunks, 6 per thread ----
    #define LOAD_STAGE(st, k0) do { \
        _Pragma("unroll") \
        for (int i = 0; i < 6; ++i) { \
            int idx = tid + i * 256; \
            if (idx < 512) { \
                int h = idx >> 8; \
                int j = idx & 255; \
                int r = j >> 2, c16 = j & 3; \
                const __half* src = (h ? g_Xlo : g_Xhi) \
                    + ((size_t)b * MAXT + row0 + r) * HIDDEN + (k0) + c16 * 8; \
                uint32_t dst = S + ((st) * A_ST_H + h * A_HL_H + r * LDT) * 2 + c16 * 16; \
                CP_ASYNC16(dst, src); \
            } else { \
                int j2 = idx - 512; \
                int h = j2 >> 9; \
                int j = j2 & 511; \
                int r = j >> 2, c16 = j & 3; \
                const __half* src = (h ? g_Wlo : g_Whi) \
                    + ((size_t)(e0 + r)) * HIDDEN + (k0) + c16 * 8; \
                uint32_t dst = S + B_BASE_B + ((st) * B_ST_H + h * B_HL_H + r * LDT) * 2 + c16 * 16; \
                CP_ASYNC16(dst, src); \
            } \
        } \
        CP_COMMIT(); \
    } while (0)

    float acc[2][4][4] = {};

    int aRow = warp_m * 32 + (lane & 15);
    int aCol = (lane >> 4) * 8;
    int bRow = warp_n * 32 + (lane & 7);
    int bCol = ((lane >> 3) & 1) * 8;

    LOAD_STAGE(0, 0);

    for (int s = 0; s < NCH; ++s) {
        int st = s & 1;
        if (s + 1 < NCH) {
            LOAD_STAGE((s + 1) & 1, (s + 1) * BK);
            CP_WAIT(1);
        } else {
            CP_WAIT(0);
        }
        __syncthreads();

        uint32_t aB = S + st * A_ST_H * 2;
        uint32_t bB = S + B_BASE_B + st * B_ST_H * 2;

        #pragma unroll
        for (int k16 = 0; k16 < 2; ++k16) {
            uint32_t ahi[2][4], alo[2][4], bhi[4][2], blo[4][2];
            #pragma unroll
            for (int mt = 0; mt < 2; ++mt) {
                uint32_t ao = aB + (((aRow + mt * 16) * LDT) + aCol + k16 * 16) * 2;
                LDSM_X4(ahi[mt], ao);
                LDSM_X4(alo[mt], ao + A_HL_H * 2);
            }
            #pragma unroll
            for (int nt = 0; nt < 4; ++nt) {
                uint32_t bo = bB + (((bRow + nt * 8) * LDT) + bCol + k16 * 16) * 2;
                LDSM_X2(bhi[nt], bo);
                LDSM_X2(blo[nt], bo + B_HL_H * 2);
            }
            #pragma unroll
            for (int mt = 0; mt < 2; ++mt)
                #pragma unroll
                for (int nt = 0; nt < 4; ++nt) {
                    MMA16816(acc[mt][nt], ahi[mt], bhi[nt]);
                    MMA16816(acc[mt][nt], ahi[mt], blo[nt]);
                    MMA16816(acc[mt][nt], alo[mt], bhi[nt]);
                }
        }
        __syncthreads();
    }

    // epilogue: p[row] += sum_n q[n]*tanh(acc + bb[n]); quad reduce; atomic
    float part[2][2] = {};
    #pragma unroll
    for (int mt = 0; mt < 2; ++mt)
        #pragma unroll
        for (int nt = 0; nt < 4; ++nt) {
            int nl = warp_n * 32 + nt * 8 + (lane & 3) * 2;
            float q0 = qs[nl], q1 = qs[nl + 1];
            float b0 = bbs[nl], b1 = bbs[nl + 1];
            part[mt][0] += q0 * tanhf(acc[mt][nt][0] + b0)
                         + q1 * tanhf(acc[mt][nt][1] + b1);
            part[mt][1] += q0 * tanhf(acc[mt][nt][2] + b0)
                         + q1 * tanhf(acc[mt][nt][3] + b1);
        }
    #pragma unroll
    for (int mt = 0; mt < 2; ++mt)
        #pragma unroll
        for (int i = 0; i < 2; ++i) {
            part[mt][i] += __shfl_xor_sync(0xffffffffu, part[mt][i], 1);
            part[mt][i] += __shfl_xor_sync(0xffffffffu, part[mt][i], 2);
        }
    if ((lane & 3) == 0) {
        #pragma unroll
        for (int mt = 0; mt < 2; ++mt)
            #pragma unroll
            for (int i = 0; i < 2; ++i) {
                int r = row0 + warp_m * 32 + mt * 16 + i * 8 + (lane >> 2);
                if (r < Tb) atomicAdd(&g_scores[b * SEQ + r], part[mt][i]);
            }
    }
}

// ============================================================
// Kernel C: warp-per-chunk softmax + weighted sum + LayerNorm
// grid = 512 blocks, 256 threads (8 warps = 8 chunks/block)
// ============================================================
__global__ void __launch_bounds__(256)
chunk_embed_kernel(const float* __restrict__ tokens,
                   const float* __restrict__ ln_w,
                   const float* __restrict__ ln_b,
                   float* __restrict__ out_chunk) {
    int warp = threadIdx.x >> 5;
    int lane = threadIdx.x & 31;
    int bc = blockIdx.x * 8 + warp;
    int b = bc >> 7;
    int len = g_len[bc];
    int start = g_start[bc];
    float s0 = g_s0;

    float sc[LC];
    #pragma unroll
    for (int j = 0; j < LC; j++) {
        if (j < len) {
            int t = start + j;
            if (t > SEQ - 1) t = SEQ - 1;
            if (t < 0) t = 0;
            sc[j] = g_scores[b * SEQ + t];
        } else {
            sc[j] = s0;
        }
    }
    float m = sc[0];
    #pragma unroll
    for (int j = 1; j < LC; j++) m = fmaxf(m, sc[j]);
    float den = 0.0f;
    float w8[LC];
    #pragma unroll
    for (int j = 0; j < LC; j++) { w8[j] = expf(sc[j] - m); den += w8[j]; }
    float inv_den = 1.0f / den;

    float v[24];
    #pragma unroll
    for (int i = 0; i < 24; ++i) v[i] = 0.0f;
    #pragma unroll
    for (int j = 0; j < LC; j++) {
        if (j < len) {
            int t = start + j;
            if (t > SEQ - 1) t = SEQ - 1;
            if (t < 0) t = 0;
            float wj = w8[j] * inv_den;
            const float* row = tokens + ((size_t)b * SEQ + t) * HIDDEN;
            #pragma unroll
            for (int i = 0; i < 24; ++i)
                v[i] += wj * row[i * 32 + lane];
        }
    }

    float tot = 0.0f;
    #pragma unroll
    for (int i = 0; i < 24; ++i) tot += v[i];
    #pragma unroll
    for (int off = 16; off > 0; off >>= 1)
        tot += __shfl_xor_sync(0xffffffffu, tot, off);
    float u = tot * (1.0f / HIDDEN);

    float ssq = 0.0f;
    #pragma unroll
    for (int i = 0; i < 24; ++i) { v[i] -= u; ssq += v[i] * v[i]; }
    #pragma unroll
    for (int off = 16; off > 0; off >>= 1)
        ssq += __shfl_xor_sync(0xffffffffu, ssq, off);
    float inv = rsqrtf(ssq * (1.0f / HIDDEN) + LN_EPS);

    float* outp = out_chunk + (size_t)bc * HIDDEN;
    #pragma unroll
    for (int i = 0; i < 24; ++i) {
        int d = i * 32 + lane;
        outp[d] = ln_w[d] * (v[i] * inv) + ln_b[d];
    }
}

// ============================================================
// Kernel D: sentence max, 2-stage, float4
// ============================================================
__global__ void __launch_bounds__(192)
sent_partial_kernel(const float* __restrict__ chunk_feat) {
    int g = blockIdx.x;     // 0..7
    int b = blockIdx.y;
    int d4 = threadIdx.x;   // 0..191
    const float4* p = (const float4*)(chunk_feat + ((size_t)b * NCHUNK + g * 16) * HIDDEN) + d4;
    float4 m = p[0];
    #pragma unroll
    for (int c = 1; c < 16; ++c) {
        float4 x = p[(size_t)c * (HIDDEN / 4)];
        m.x = fmaxf(m.x, x.x); m.y = fmaxf(m.y, x.y);
        m.z = fmaxf(m.z, x.z); m.w = fmaxf(m.w, x.w);
    }
    ((float4*)g_pmax)[((size_t)g * BATCH + b) * (HIDDEN / 4) + d4] = m;
}

__global__ void __launch_bounds__(192)
sent_final_kernel(float* __restrict__ out) {
    int b = blockIdx.x;
    int d4 = threadIdx.x;
    const float4* p = (const float4*)g_pmax;
    float4 m = p[(size_t)b * (HIDDEN / 4) + d4];
    #pragma unroll
    for (int g = 1; g < 8; ++g) {
        float4 x = p[((size_t)g * BATCH + b) * (HIDDEN / 4) + d4];
        m.x = fmaxf(m.x, x.x); m.y = fmaxf(m.y, x.y);
        m.z = fmaxf(m.z, x.z); m.w = fmaxf(m.w, x.w);
    }
    ((float4*)(out + (size_t)b * HIDDEN))[d4] = m;
}

// ============================================================
extern "C" void kernel_launch(void* const* d_in, const int* in_sizes, int n_in,
                              void* d_out, int out_size) {
    const float* tokens    = (const float*)d_in[0];
    const int*   chunk_lens= (const int*)d_in[1];
    const float* dense_w   = (const float*)d_in[2];
    const float* dense_b   = (const float*)d_in[3];
    const float* attn_bias = (const float*)d_in[4];
    const float* query     = (const float*)d_in[5];
    const float* ln_w      = (const float*)d_in[6];
    const float* ln_b      = (const float*)d_in[7];
    float* out = (float*)d_out;

    float* out_chunk = out;
    float* out_sent  = out + (size_t)BATCH * NCHUNK * HIDDEN;

    static bool attr_set = false;
    if (!attr_set) {
        cudaFuncSetAttribute(gemm_hmma_kernel,
                             cudaFuncAttributeMaxDynamicSharedMemorySize, SMEM_GEMM);
        attr_set = true;
    }

    prep_kernel<<<BATCH, NCHUNK>>>(chunk_lens, dense_b, attn_bias, query);

    convert_kernel<<<816, 256>>>(tokens, dense_w);

    dim3 gB(HIDDEN / BN, MAXT / BM, BATCH);   // (6, 6, 32), early exit on T_b
    gemm_hmma_kernel<<<gB, 256, SMEM_GEMM>>>(dense_b, attn_bias, query);

    chunk_embed_kernel<<<BATCH * NCHUNK / 8, 256>>>(tokens, ln_w, ln_b, out_chunk);

    dim3 gP(8, BATCH);
    sent_partial_kernel<<<gP, 192>>>(out_chunk);
    sent_final_kernel<<<BATCH, 192>>>(out_sent);
}

// round 6
// speedup vs baseline: 2.3914x; 1.0155x over previous
#include <cuda_runtime.h>
#include <cuda_fp16.h>
#include <math.h>
#include <stdint.h>

#define HIDDEN 768
#define BATCH 32
#define SEQ 512
#define NCHUNK 128
#define LC 8
#define LN_EPS 1e-12f
#define MAXT 384

// GEMM tiling
#define BM 64
#define BN 128
#define BK 32
#define NCH (HIDDEN / BK)   // 24
#define LDT 40              // smem row stride in halves (80B)

// 3-stage smem layout (bytes, per stage): [Ahi 5120][Alo 5120][Bhi 10240][Blo 10240]
#define STG_B    30720
#define SMEM_GEMM (3 * STG_B)   // 92160

// ---- device scratch ----
__device__ float g_scores[BATCH * SEQ];
__device__ int   g_start[BATCH * NCHUNK];
__device__ int   g_len[BATCH * NCHUNK];
__device__ int   g_T[BATCH];
__device__ float g_s0;
__device__ unsigned int g_maxu[BATCH * HIDDEN];
__device__ __half g_Xhi[BATCH * MAXT * HIDDEN];
__device__ __half g_Xlo[BATCH * MAXT * HIDDEN];
__device__ __half g_Whi[HIDDEN * HIDDEN];
__device__ __half g_Wlo[HIDDEN * HIDDEN];

__device__ __forceinline__ uint32_t smem_u32(const void* p) {
    uint32_t a;
    asm("{ .reg .u64 t; cvta.to.shared.u64 t, %1; cvt.u32.u64 %0, t; }" : "=r"(a) : "l"(p));
    return a;
}

__device__ __forceinline__ uint32_t h2_as_u32(__half2 h) {
    union { __half2 h; uint32_t u; } cvt;
    cvt.h = h;
    return cvt.u;
}

// monotonic float<->uint key (uint order == float order)
__device__ __forceinline__ unsigned int fkey(float f) {
    unsigned int b = __float_as_uint(f);
    return (b & 0x80000000u) ? ~b : (b | 0x80000000u);
}
__device__ __forceinline__ float funkey(unsigned int k) {
    unsigned int b = (k & 0x80000000u) ? (k ^ 0x80000000u) : ~k;
    return __uint_as_float(b);
}

#define LDSM_X4(r, addr) \
    asm volatile("ldmatrix.sync.aligned.m8n8.x4.shared.b16 {%0,%1,%2,%3}, [%4];" \
        : "=r"((r)[0]), "=r"((r)[1]), "=r"((r)[2]), "=r"((r)[3]) : "r"(addr))

#define LDSM_X2(r, addr) \
    asm volatile("ldmatrix.sync.aligned.m8n8.x2.shared.b16 {%0,%1}, [%2];" \
        : "=r"((r)[0]), "=r"((r)[1]) : "r"(addr))

#define MMA16816(d, a, bf) \
    asm volatile("mma.sync.aligned.m16n8k16.row.col.f32.f16.f16.f32 " \
        "{%0,%1,%2,%3}, {%4,%5,%6,%7}, {%8,%9}, {%0,%1,%2,%3};" \
        : "+f"((d)[0]), "+f"((d)[1]), "+f"((d)[2]), "+f"((d)[3]) \
        : "r"((a)[0]), "r"((a)[1]), "r"((a)[2]), "r"((a)[3]), \
          "r"((bf)[0]), "r"((bf)[1]))

#define CP_ASYNC16(dst, src) \
    asm volatile("cp.async.cg.shared.global [%0], [%1], 16;" :: "r"(dst), "l"(src))
#define CP_COMMIT() asm volatile("cp.async.commit_group;" ::: "memory")
#define CP_WAIT(n)  asm volatile("cp.async.wait_group %0;" :: "n"(n) : "memory")

__device__ __forceinline__ void split_pack(float4 v, uint2& hi, uint2& lo) {
    __half2 h01 = __floats2half2_rn(v.x, v.y);
    __half2 h23 = __floats2half2_rn(v.z, v.w);
    float2 f01 = __half22float2(h01);
    float2 f23 = __half22float2(h23);
    __half2 l01 = __floats2half2_rn(v.x - f01.x, v.y - f01.y);
    __half2 l23 = __floats2half2_rn(v.z - f23.x, v.w - f23.y);
    hi.x = h2_as_u32(h01); hi.y = h2_as_u32(h23);
    lo.x = h2_as_u32(l01); lo.y = h2_as_u32(l23);
}

// ============================================================
// Kernel 1: setup — fused X/W split-convert + prefix scan + inits
// grid = 848 x 256:
//   blk 0..767   : X convert (b = blk/24, 16 rows), T_b computed inline
//   blk 768..815 : W convert (16 rows each)
//   blk 816..847 : per-batch prep (scan, zero scores, zero maxu, s0)
// ============================================================
__global__ void __launch_bounds__(256)
setup_kernel(const float* __restrict__ tokens, const float* __restrict__ W,
             const int* __restrict__ chunk_lens,
             const float* __restrict__ dense_b,
             const float* __restrict__ attn_bias,
             const float* __restrict__ query) {
    int blk = blockIdx.x;
    int tid = threadIdx.x;

    if (blk < 768) {
        int b = blk / 24;
        int rg = blk - b * 24;
        int row0 = rg * 16;
        // inline T_b = clamp(sum lens, 0, SEQ)
        __shared__ int wsum[8];
        __shared__ int sT;
        int v = (tid < NCHUNK) ? chunk_lens[b * NCHUNK + tid] : 0;
        #pragma unroll
        for (int off = 16; off > 0; off >>= 1)
            v += __shfl_xor_sync(0xffffffffu, v, off);
        if ((tid & 31) == 0) wsum[tid >> 5] = v;
        __syncthreads();
        if (tid == 0) {
            int t = wsum[0] + wsum[1] + wsum[2] + wsum[3];
            if (t > SEQ) t = SEQ;
            if (t < 0) t = 0;
            sT = t;
        }
        __syncthreads();
        if (row0 >= sT) return;
        const float4* src = (const float4*)(tokens + ((size_t)b * SEQ + row0) * HIDDEN);
        size_t dst0 = ((size_t)b * MAXT + row0) * HIDDEN;
        #pragma unroll
        for (int i = 0; i < 12; ++i) {
            int idx = tid + i * 256;
            float4 val = src[idx];
            uint2 hi, lo;
            split_pack(val, hi, lo);
            *(uint2*)&g_Xhi[dst0 + (size_t)idx * 4] = hi;
            *(uint2*)&g_Xlo[dst0 + (size_t)idx * 4] = lo;
        }
    } else if (blk < 816) {
        int row0 = (blk - 768) * 16;
        const float4* src = (const float4*)(W + (size_t)row0 * HIDDEN);
        size_t dst0 = (size_t)row0 * HIDDEN;
        #pragma unroll
        for (int i = 0; i < 12; ++i) {
            int idx = tid + i * 256;
            float4 val = src[idx];
            uint2 hi, lo;
            split_pack(val, hi, lo);
            *(uint2*)&g_Whi[dst0 + (size_t)idx * 4] = hi;
            *(uint2*)&g_Wlo[dst0 + (size_t)idx * 4] = lo;
        }
    } else {
        int b = blk - 816;
        __shared__ int sc[NCHUNK];
        int len = 0;
        if (tid < NCHUNK) {
            len = chunk_lens[b * NCHUNK + tid];
            sc[tid] = len;
        }
        __syncthreads();
        for (int off = 1; off < NCHUNK; off <<= 1) {
            int v = (tid < NCHUNK && tid >= off) ? sc[tid - off] : 0;
            __syncthreads();
            if (tid < NCHUNK) sc[tid] += v;
            __syncthreads();
        }
        if (tid < NCHUNK) {
            int incl = sc[tid];
            g_start[b * NCHUNK + tid] = incl - len;
            int le = len;
            if (le < 0) le = 0;
            if (le > LC) le = LC;
            g_len[b * NCHUNK + tid] = le;
            if (tid == NCHUNK - 1) {
                int T = incl;
                if (T > SEQ) T = SEQ;
                if (T < 0) T = 0;
                g_T[b] = T;
            }
        }
        for (int t = tid; t < SEQ; t += 256) g_scores[b * SEQ + t] = 0.0f;
        for (int d = tid; d < HIDDEN; d += 256) g_maxu[b * HIDDEN + d] = 0u;

        if (b == 0) {
            float acc = 0.0f;
            for (int e = tid; e < HIDDEN; e += 256)
                acc += query[e] * tanhf(dense_b[e] + attn_bias[e]);
            #pragma unroll
            for (int off = 16; off > 0; off >>= 1)
                acc += __shfl_xor_sync(0xffffffffu, acc, off);
            __shared__ float red[8];
            if ((tid & 31) == 0) red[tid >> 5] = acc;
            __syncthreads();
            if (tid == 0) {
                float s = 0.0f;
                #pragma unroll
                for (int w = 0; w < 8; ++w) s += red[w];
                g_s0 = s;
            }
        }
    }
}

// ============================================================
// Kernel 2: HMMA GEMM (pre-split operands), 3-stage pipeline, 1 sync/slab
// grid = (6 n-tiles, 6 m-tiles, 32 batches), 256 threads (8 warps 2m x 4n)
// ============================================================
__global__ void __launch_bounds__(256, 2)
gemm_hmma_kernel(const float* __restrict__ dense_b,
                 const float* __restrict__ attn_bias,
                 const float* __restrict__ query) {
    int b = blockIdx.z;
    int Tb = g_T[b];
    int row0 = blockIdx.y * BM;
    if (row0 >= Tb) return;
    int e0 = blockIdx.x * BN;

    extern __shared__ char smem[];
    uint32_t S = smem_u32(smem);
    __shared__ float qs[BN], bbs[BN];

    int tid = threadIdx.x;
    int wid = tid >> 5;
    int lane = tid & 31;
    int warp_m = wid & 1;
    int warp_n = wid >> 1;

    if (tid < BN) {
        int e = e0 + tid;
        qs[tid]  = query[e];
        bbs[tid] = dense_b[e] + attn_bias[e];
    }

    // stage loader: 1536 16B chunks, 6 per thread
    #define LOAD_STAGE(st, k0) do { \
        uint32_t base_ = S + (st) * STG_B; \
        _Pragma("unroll") \
        for (int i = 0; i < 6; ++i) { \
            int idx = tid + i * 256; \
            if (idx < 512) { \
                int h = idx >> 8; \
                int j = idx & 255; \
                int r = j >> 2, c16 = j & 3; \
                const __half* src = (h ? g_Xlo : g_Xhi) \
                    + ((size_t)b * MAXT + row0 + r) * HIDDEN + (k0) + c16 * 8; \
                CP_ASYNC16(base_ + h * 5120 + r * 80 + c16 * 16, src); \
            } else { \
                int j2 = idx - 512; \
                int h = j2 >> 9; \
                int j = j2 & 511; \
                int r = j >> 2, c16 = j & 3; \
                const __half* src = (h ? g_Wlo : g_Whi) \
                    + ((size_t)(e0 + r)) * HIDDEN + (k0) + c16 * 8; \
                CP_ASYNC16(base_ + 10240 + h * 10240 + r * 80 + c16 * 16, src); \
            } \
        } \
        CP_COMMIT(); \
    } while (0)

    float acc[2][4][4] = {};

    int aRow = warp_m * 32 + (lane & 15);
    int aCol = (lane >> 4) * 8;
    int bRow = warp_n * 32 + (lane & 7);
    int bCol = ((lane >> 3) & 1) * 8;

    LOAD_STAGE(0, 0);
    LOAD_STAGE(1, BK);

    int st = 0;
    for (int s = 0; s < NCH; ++s) {
        if (s < NCH - 1) { CP_WAIT(1); } else { CP_WAIT(0); }
        __syncthreads();

        // prefetch stage s+2 (its buffer was consumed in iter s-1)
        if (s + 2 < NCH) {
            int st2 = st + 2; if (st2 >= 3) st2 -= 3;
            LOAD_STAGE(st2, (s + 2) * BK);
        }

        uint32_t aB = S + st * STG_B;
        uint32_t bB = aB + 10240;

        #pragma unroll
        for (int k16 = 0; k16 < 2; ++k16) {
            uint32_t ahi[2][4], alo[2][4], bhi[4][2], blo[4][2];
            #pragma unroll
            for (int mt = 0; mt < 2; ++mt) {
                uint32_t ao = aB + (((aRow + mt * 16) * LDT) + aCol + k16 * 16) * 2;
                LDSM_X4(ahi[mt], ao);
                LDSM_X4(alo[mt], ao + 5120);
            }
            #pragma unroll
            for (int nt = 0; nt < 4; ++nt) {
                uint32_t bo = bB + (((bRow + nt * 8) * LDT) + bCol + k16 * 16) * 2;
                LDSM_X2(bhi[nt], bo);
                LDSM_X2(blo[nt], bo + 10240);
            }
            #pragma unroll
            for (int mt = 0; mt < 2; ++mt)
                #pragma unroll
                for (int nt = 0; nt < 4; ++nt) {
                    MMA16816(acc[mt][nt], ahi[mt], bhi[nt]);
                    MMA16816(acc[mt][nt], ahi[mt], blo[nt]);
                    MMA16816(acc[mt][nt], alo[mt], bhi[nt]);
                }
        }
        if (++st == 3) st = 0;
    }

    // epilogue
    float part[2][2] = {};
    #pragma unroll
    for (int mt = 0; mt < 2; ++mt)
        #pragma unroll
        for (int nt = 0; nt < 4; ++nt) {
            int nl = warp_n * 32 + nt * 8 + (lane & 3) * 2;
            float q0 = qs[nl], q1 = qs[nl + 1];
            float b0 = bbs[nl], b1 = bbs[nl + 1];
            part[mt][0] += q0 * tanhf(acc[mt][nt][0] + b0)
                         + q1 * tanhf(acc[mt][nt][1] + b1);
            part[mt][1] += q0 * tanhf(acc[mt][nt][2] + b0)
                         + q1 * tanhf(acc[mt][nt][3] + b1);
        }
    #pragma unroll
    for (int mt = 0; mt < 2; ++mt)
        #pragma unroll
        for (int i = 0; i < 2; ++i) {
            part[mt][i] += __shfl_xor_sync(0xffffffffu, part[mt][i], 1);
            part[mt][i] += __shfl_xor_sync(0xffffffffu, part[mt][i], 2);
        }
    if ((lane & 3) == 0) {
        #pragma unroll
        for (int mt = 0; mt < 2; ++mt)
            #pragma unroll
            for (int i = 0; i < 2; ++i) {
                int r = row0 + warp_m * 32 + mt * 16 + i * 8 + (lane >> 2);
                if (r < Tb) atomicAdd(&g_scores[b * SEQ + r], part[mt][i]);
            }
    }
}

// ============================================================
// Kernel 3: warp-per-chunk softmax + weighted sum + LayerNorm
//           + fused sentence-max via monotonic-uint atomicMax
// grid = 1024 blocks, 128 threads (4 warps = 4 chunks/block)
// ============================================================
__global__ void __launch_bounds__(128)
chunk_embed_kernel(const float* __restrict__ tokens,
                   const float* __restrict__ ln_w,
                   const float* __restrict__ ln_b,
                   float* __restrict__ out_chunk) {
    int warp = threadIdx.x >> 5;
    int lane = threadIdx.x & 31;
    int bc = blockIdx.x * 4 + warp;
    int b = bc >> 7;
    int len = g_len[bc];
    int start = g_start[bc];
    float s0 = g_s0;

    float sc[LC];
    #pragma unroll
    for (int j = 0; j < LC; j++) {
        if (j < len) {
            int t = start + j;
            if (t > SEQ - 1) t = SEQ - 1;
            if (t < 0) t = 0;
            sc[j] = g_scores[b * SEQ + t];
        } else {
            sc[j] = s0;
        }
    }
    float m = sc[0];
    #pragma unroll
    for (int j = 1; j < LC; j++) m = fmaxf(m, sc[j]);
    float den = 0.0f;
    float w8[LC];
    #pragma unroll
    for (int j = 0; j < LC; j++) { w8[j] = expf(sc[j] - m); den += w8[j]; }
    float inv_den = 1.0f / den;

    float v[24];
    #pragma unroll
    for (int i = 0; i < 24; ++i) v[i] = 0.0f;
    #pragma unroll
    for (int j = 0; j < LC; j++) {
        if (j < len) {
            int t = start + j;
            if (t > SEQ - 1) t = SEQ - 1;
            if (t < 0) t = 0;
            float wj = w8[j] * inv_den;
            const float* row = tokens + ((size_t)b * SEQ + t) * HIDDEN;
            #pragma unroll
            for (int i = 0; i < 24; ++i)
                v[i] += wj * row[i * 32 + lane];
        }
    }

    float tot = 0.0f;
    #pragma unroll
    for (int i = 0; i < 24; ++i) tot += v[i];
    #pragma unroll
    for (int off = 16; off > 0; off >>= 1)
        tot += __shfl_xor_sync(0xffffffffu, tot, off);
    float u = tot * (1.0f / HIDDEN);

    float ssq = 0.0f;
    #pragma unroll
    for (int i = 0; i < 24; ++i) { v[i] -= u; ssq += v[i] * v[i]; }
    #pragma unroll
    for (int off = 16; off > 0; off >>= 1)
        ssq += __shfl_xor_sync(0xffffffffu, ssq, off);
    float inv = rsqrtf(ssq * (1.0f / HIDDEN) + LN_EPS);

    float* outp = out_chunk + (size_t)bc * HIDDEN;
    unsigned int* mx = &g_maxu[b * HIDDEN];
    #pragma unroll
    for (int i = 0; i < 24; ++i) {
        int d = i * 32 + lane;
        float o = ln_w[d] * (v[i] * inv) + ln_b[d];
        outp[d] = o;
        atomicMax(&mx[d], fkey(o));
    }
}

// ============================================================
// Kernel 4: decode sentence max
// ============================================================
__global__ void __launch_bounds__(256)
sent_decode_kernel(float* __restrict__ out) {
    int b = blockIdx.x;
    int tid = threadIdx.x;
    #pragma unroll
    for (int i = 0; i < 3; ++i) {
        int d = tid + i * 256;
        out[b * HIDDEN + d] = funkey(g_maxu[b * HIDDEN + d]);
    }
}

// ============================================================
extern "C" void kernel_launch(void* const* d_in, const int* in_sizes, int n_in,
                              void* d_out, int out_size) {
    const float* tokens    = (const float*)d_in[0];
    const int*   chunk_lens= (const int*)d_in[1];
    const float* dense_w   = (const float*)d_in[2];
    const float* dense_b   = (const float*)d_in[3];
    const float* attn_bias = (const float*)d_in[4];
    const float* query     = (const float*)d_in[5];
    const float* ln_w      = (const float*)d_in[6];
    const float* ln_b      = (const float*)d_in[7];
    float* out = (float*)d_out;

    float* out_chunk = out;
    float* out_sent  = out + (size_t)BATCH * NCHUNK * HIDDEN;

    static bool attr_set = false;
    if (!attr_set) {
        cudaFuncSetAttribute(gemm_hmma_kernel,
                             cudaFuncAttributeMaxDynamicSharedMemorySize, SMEM_GEMM);
        attr_set = true;
    }

    setup_kernel<<<848, 256>>>(tokens, dense_w, chunk_lens, dense_b, attn_bias, query);

    dim3 gB(HIDDEN / BN, MAXT / BM, BATCH);   // (6, 6, 32), early exit on T_b
    gemm_hmma_kernel<<<gB, 256, SMEM_GEMM>>>(dense_b, attn_bias, query);

    chunk_embed_kernel<<<BATCH * NCHUNK / 4, 128>>>(tokens, ln_w, ln_b, out_chunk);

    sent_decode_kernel<<<BATCH, 256>>>(out_sent);
}

// round 7
// speedup vs baseline: 2.4072x; 1.0066x over previous
#include <cuda_runtime.h>
#include <cuda_fp16.h>
#include <math.h>
#include <stdint.h>

#define HIDDEN 768
#define BATCH 32
#define SEQ 512
#define NCHUNK 128
#define LC 8
#define LN_EPS 1e-12f
#define MAXT 384

// GEMM tiling
#define BM 64
#define BN 128
#define BK 32
#define NCH (HIDDEN / BK)   // 24
#define LDT 40              // smem row stride in halves (80B)

// 3-stage smem layout (bytes/stage): [Ahi 5120][Alo 5120][Bhi 10240][Blo 10240]
#define STG_B    30720
#define SMEM_GEMM (3 * STG_B)   // 92160

// ---- device scratch ----
__device__ float g_scores[BATCH * SEQ];
__device__ int   g_start[BATCH * NCHUNK];
__device__ int   g_len[BATCH * NCHUNK];
__device__ int   g_T[BATCH];
__device__ float g_s0;
__device__ unsigned int g_maxu[BATCH * HIDDEN];
__device__ int   g_cnt[BATCH];
__device__ __half g_Xhi[BATCH * MAXT * HIDDEN];
__device__ __half g_Xlo[BATCH * MAXT * HIDDEN];
__device__ __half g_Whi[HIDDEN * HIDDEN];
__device__ __half g_Wlo[HIDDEN * HIDDEN];

__device__ __forceinline__ uint32_t smem_u32(const void* p) {
    uint32_t a;
    asm("{ .reg .u64 t; cvta.to.shared.u64 t, %1; cvt.u32.u64 %0, t; }" : "=r"(a) : "l"(p));
    return a;
}

__device__ __forceinline__ uint32_t h2_as_u32(__half2 h) {
    union { __half2 h; uint32_t u; } cvt;
    cvt.h = h;
    return cvt.u;
}
__device__ __forceinline__ __half2 u32_as_h2(uint32_t u) {
    union { uint32_t u; __half2 h; } cvt;
    cvt.u = u;
    return cvt.h;
}

// monotonic float<->uint key
__device__ __forceinline__ unsigned int fkey(float f) {
    unsigned int b = __float_as_uint(f);
    return (b & 0x80000000u) ? ~b : (b | 0x80000000u);
}
__device__ __forceinline__ float funkey(unsigned int k) {
    unsigned int b = (k & 0x80000000u) ? (k ^ 0x80000000u) : ~k;
    return __uint_as_float(b);
}

#define LDSM_X4(r, addr) \
    asm volatile("ldmatrix.sync.aligned.m8n8.x4.shared.b16 {%0,%1,%2,%3}, [%4];" \
        : "=r"((r)[0]), "=r"((r)[1]), "=r"((r)[2]), "=r"((r)[3]) : "r"(addr))

#define MMA16816(d, a, bf) \
    asm volatile("mma.sync.aligned.m16n8k16.row.col.f32.f16.f16.f32 " \
        "{%0,%1,%2,%3}, {%4,%5,%6,%7}, {%8,%9}, {%0,%1,%2,%3};" \
        : "+f"((d)[0]), "+f"((d)[1]), "+f"((d)[2]), "+f"((d)[3]) \
        : "r"((a)[0]), "r"((a)[1]), "r"((a)[2]), "r"((a)[3]), \
          "r"((bf)[0]), "r"((bf)[1]))

#define MMA16816H(d, a, bf) \
    asm volatile("mma.sync.aligned.m16n8k16.row.col.f16.f16.f16.f16 " \
        "{%0,%1}, {%2,%3,%4,%5}, {%6,%7}, {%0,%1};" \
        : "+r"((d)[0]), "+r"((d)[1]) \
        : "r"((a)[0]), "r"((a)[1]), "r"((a)[2]), "r"((a)[3]), \
          "r"((bf)[0]), "r"((bf)[1]))

#define CP_ASYNC16(dst, src) \
    asm volatile("cp.async.cg.shared.global [%0], [%1], 16;" :: "r"(dst), "l"(src))
#define CP_COMMIT() asm volatile("cp.async.commit_group;" ::: "memory")
#define CP_WAIT(n)  asm volatile("cp.async.wait_group %0;" :: "n"(n) : "memory")

__device__ __forceinline__ void split_pack(float4 v, uint2& hi, uint2& lo) {
    __half2 h01 = __floats2half2_rn(v.x, v.y);
    __half2 h23 = __floats2half2_rn(v.z, v.w);
    float2 f01 = __half22float2(h01);
    float2 f23 = __half22float2(h23);
    __half2 l01 = __floats2half2_rn(v.x - f01.x, v.y - f01.y);
    __half2 l23 = __floats2half2_rn(v.z - f23.x, v.w - f23.y);
    hi.x = h2_as_u32(h01); hi.y = h2_as_u32(h23);
    lo.x = h2_as_u32(l01); lo.y = h2_as_u32(l23);
}

// ============================================================
// Kernel 1: setup — fused X/W split-convert + prefix scan + inits
// ============================================================
__global__ void __launch_bounds__(256)
setup_kernel(const float* __restrict__ tokens, const float* __restrict__ W,
             const int* __restrict__ chunk_lens,
             const float* __restrict__ dense_b,
             const float* __restrict__ attn_bias,
             const float* __restrict__ query) {
    int blk = blockIdx.x;
    int tid = threadIdx.x;

    if (blk < 768) {
        int b = blk / 24;
        int rg = blk - b * 24;
        int row0 = rg * 16;
        __shared__ int wsum[8];
        __shared__ int sT;
        int v = (tid < NCHUNK) ? chunk_lens[b * NCHUNK + tid] : 0;
        #pragma unroll
        for (int off = 16; off > 0; off >>= 1)
            v += __shfl_xor_sync(0xffffffffu, v, off);
        if ((tid & 31) == 0) wsum[tid >> 5] = v;
        __syncthreads();
        if (tid == 0) {
            int t = wsum[0] + wsum[1] + wsum[2] + wsum[3];
            if (t > SEQ) t = SEQ;
            if (t < 0) t = 0;
            sT = t;
        }
        __syncthreads();
        if (row0 >= sT) return;
        const float4* src = (const float4*)(tokens + ((size_t)b * SEQ + row0) * HIDDEN);
        size_t dst0 = ((size_t)b * MAXT + row0) * HIDDEN;
        #pragma unroll
        for (int i = 0; i < 12; ++i) {
            int idx = tid + i * 256;
            float4 val = src[idx];
            uint2 hi, lo;
            split_pack(val, hi, lo);
            *(uint2*)&g_Xhi[dst0 + (size_t)idx * 4] = hi;
            *(uint2*)&g_Xlo[dst0 + (size_t)idx * 4] = lo;
        }
    } else if (blk < 816) {
        int row0 = (blk - 768) * 16;
        const float4* src = (const float4*)(W + (size_t)row0 * HIDDEN);
        size_t dst0 = (size_t)row0 * HIDDEN;
        #pragma unroll
        for (int i = 0; i < 12; ++i) {
            int idx = tid + i * 256;
            float4 val = src[idx];
            uint2 hi, lo;
            split_pack(val, hi, lo);
            *(uint2*)&g_Whi[dst0 + (size_t)idx * 4] = hi;
            *(uint2*)&g_Wlo[dst0 + (size_t)idx * 4] = lo;
        }
    } else {
        int b = blk - 816;
        __shared__ int sc[NCHUNK];
        int len = 0;
        if (tid < NCHUNK) {
            len = chunk_lens[b * NCHUNK + tid];
            sc[tid] = len;
        }
        __syncthreads();
        for (int off = 1; off < NCHUNK; off <<= 1) {
            int v = (tid < NCHUNK && tid >= off) ? sc[tid - off] : 0;
            __syncthreads();
            if (tid < NCHUNK) sc[tid] += v;
            __syncthreads();
        }
        if (tid < NCHUNK) {
            int incl = sc[tid];
            g_start[b * NCHUNK + tid] = incl - len;
            int le = len;
            if (le < 0) le = 0;
            if (le > LC) le = LC;
            g_len[b * NCHUNK + tid] = le;
            if (tid == NCHUNK - 1) {
                int T = incl;
                if (T > SEQ) T = SEQ;
                if (T < 0) T = 0;
                g_T[b] = T;
            }
        }
        for (int t = tid; t < SEQ; t += 256) g_scores[b * SEQ + t] = 0.0f;
        for (int d = tid; d < HIDDEN; d += 256) g_maxu[b * HIDDEN + d] = 0u;
        if (tid == 0) g_cnt[b] = 0;

        if (b == 0) {
            float acc = 0.0f;
            for (int e = tid; e < HIDDEN; e += 256)
                acc += query[e] * tanhf(dense_b[e] + attn_bias[e]);
            #pragma unroll
            for (int off = 16; off > 0; off >>= 1)
                acc += __shfl_xor_sync(0xffffffffu, acc, off);
            __shared__ float red[8];
            if ((tid & 31) == 0) red[tid >> 5] = acc;
            __syncthreads();
            if (tid == 0) {
                float s = 0.0f;
                #pragma unroll
                for (int w = 0; w < 8; ++w) s += red[w];
                g_s0 = s;
            }
        }
    }
}

// ============================================================
// Kernel 2: HMMA GEMM, fp32-acc main + fp16-acc corrections
// grid = (6 n-tiles, 6 m-tiles, 32 batches), 256 threads (8 warps 2m x 4n)
// ============================================================
__global__ void __launch_bounds__(256, 2)
gemm_hmma_kernel(const float* __restrict__ dense_b,
                 const float* __restrict__ attn_bias,
                 const float* __restrict__ query) {
    int b = blockIdx.z;
    int Tb = g_T[b];
    int row0 = blockIdx.y * BM;
    if (row0 >= Tb) return;
    int e0 = blockIdx.x * BN;

    extern __shared__ char smem[];
    uint32_t S = smem_u32(smem);
    __shared__ float qs[BN], bbs[BN];

    int tid = threadIdx.x;
    int wid = tid >> 5;
    int lane = tid & 31;
    int warp_m = wid & 1;
    int warp_n = wid >> 1;

    if (tid < BN) {
        int e = e0 + tid;
        qs[tid]  = query[e];
        bbs[tid] = dense_b[e] + attn_bias[e];
    }

    #define LOAD_STAGE(st, k0) do { \
        uint32_t base_ = S + (st) * STG_B; \
        _Pragma("unroll") \
        for (int i = 0; i < 6; ++i) { \
            int idx = tid + i * 256; \
            if (idx < 512) { \
                int h = idx >> 8; \
                int j = idx & 255; \
                int r = j >> 2, c16 = j & 3; \
                const __half* src = (h ? g_Xlo : g_Xhi) \
                    + ((size_t)b * MAXT + row0 + r) * HIDDEN + (k0) + c16 * 8; \
                CP_ASYNC16(base_ + h * 5120 + r * 80 + c16 * 16, src); \
            } else { \
                int j2 = idx - 512; \
                int h = j2 >> 9; \
                int j = j2 & 511; \
                int r = j >> 2, c16 = j & 3; \
                const __half* src = (h ? g_Wlo : g_Whi) \
                    + ((size_t)(e0 + r)) * HIDDEN + (k0) + c16 * 8; \
                CP_ASYNC16(base_ + 10240 + h * 10240 + r * 80 + c16 * 16, src); \
            } \
        } \
        CP_COMMIT(); \
    } while (0)

    float acc[2][4][4] = {};
    uint32_t corr[2][4][2] = {};   // fp16x2 accumulators for cross terms

    int aRow = warp_m * 32 + (lane & 15);
    int aCol = (lane >> 4) * 8;
    // B X4 pair mapping: lanes 0-7 -> (rows n..n+7, k 0-7), 8-15 -> (same rows, k 8-15),
    // 16-23 -> rows +8, k 0-7, 24-31 -> rows +8, k 8-15
    int bRowP = warp_n * 32 + ((lane >> 4) << 3) + (lane & 7);
    int bColP = ((lane >> 3) & 1) * 8;

    LOAD_STAGE(0, 0);
    LOAD_STAGE(1, BK);

    int st = 0;
    for (int s = 0; s < NCH; ++s) {
        if (s < NCH - 1) { CP_WAIT(1); } else { CP_WAIT(0); }
        __syncthreads();

        if (s + 2 < NCH) {
            int st2 = st + 2; if (st2 >= 3) st2 -= 3;
            LOAD_STAGE(st2, (s + 2) * BK);
        }

        uint32_t aB = S + st * STG_B;
        uint32_t bB = aB + 10240;

        #pragma unroll
        for (int k16 = 0; k16 < 2; ++k16) {
            uint32_t ahi[2][4], alo[2][4], bhi[2][4], blo[2][4];
            #pragma unroll
            for (int mt = 0; mt < 2; ++mt) {
                uint32_t ao = aB + (uint32_t)((aRow + mt * 16) * 80 + (aCol + k16 * 16) * 2);
                LDSM_X4(ahi[mt], ao);
                LDSM_X4(alo[mt], ao + 5120);
            }
            #pragma unroll
            for (int p = 0; p < 2; ++p) {
                uint32_t bo = bB + (uint32_t)((bRowP + p * 16) * 80 + (bColP + k16 * 16) * 2);
                LDSM_X4(bhi[p], bo);
                LDSM_X4(blo[p], bo + 10240);
            }
            // main term (fp32 acc)
            #pragma unroll
            for (int mt = 0; mt < 2; ++mt)
                #pragma unroll
                for (int nt = 0; nt < 4; ++nt)
                    MMA16816(acc[mt][nt], ahi[mt], &bhi[nt >> 1][(nt & 1) * 2]);
            // cross terms (fp16 acc)
            #pragma unroll
            for (int mt = 0; mt < 2; ++mt)
                #pragma unroll
                for (int nt = 0; nt < 4; ++nt)
                    MMA16816H(corr[mt][nt], ahi[mt], &blo[nt >> 1][(nt & 1) * 2]);
            #pragma unroll
            for (int mt = 0; mt < 2; ++mt)
                #pragma unroll
                for (int nt = 0; nt < 4; ++nt)
                    MMA16816H(corr[mt][nt], alo[mt], &bhi[nt >> 1][(nt & 1) * 2]);
        }
        if (++st == 3) st = 0;
    }

    // fold fp16 corrections into fp32 accumulators
    #pragma unroll
    for (int mt = 0; mt < 2; ++mt)
        #pragma unroll
        for (int nt = 0; nt < 4; ++nt) {
            float2 c01 = __half22float2(u32_as_h2(corr[mt][nt][0]));
            float2 c23 = __half22float2(u32_as_h2(corr[mt][nt][1]));
            acc[mt][nt][0] += c01.x; acc[mt][nt][1] += c01.y;
            acc[mt][nt][2] += c23.x; acc[mt][nt][3] += c23.y;
        }

    // epilogue: p[row] += sum_n q[n]*tanh(acc + bb[n]); quad reduce; atomic
    float part[2][2] = {};
    #pragma unroll
    for (int mt = 0; mt < 2; ++mt)
        #pragma unroll
        for (int nt = 0; nt < 4; ++nt) {
            int nl = warp_n * 32 + nt * 8 + (lane & 3) * 2;
            float q0 = qs[nl], q1 = qs[nl + 1];
            float b0 = bbs[nl], b1 = bbs[nl + 1];
            part[mt][0] += q0 * tanhf(acc[mt][nt][0] + b0)
                         + q1 * tanhf(acc[mt][nt][1] + b1);
            part[mt][1] += q0 * tanhf(acc[mt][nt][2] + b0)
                         + q1 * tanhf(acc[mt][nt][3] + b1);
        }
    #pragma unroll
    for (int mt = 0; mt < 2; ++mt)
        #pragma unroll
        for (int i = 0; i < 2; ++i) {
            part[mt][i] += __shfl_xor_sync(0xffffffffu, part[mt][i], 1);
            part[mt][i] += __shfl_xor_sync(0xffffffffu, part[mt][i], 2);
        }
    if ((lane & 3) == 0) {
        #pragma unroll
        for (int mt = 0; mt < 2; ++mt)
            #pragma unroll
            for (int i = 0; i < 2; ++i) {
                int r = row0 + warp_m * 32 + mt * 16 + i * 8 + (lane >> 2);
                if (r < Tb) atomicAdd(&g_scores[b * SEQ + r], part[mt][i]);
            }
    }
}

// ============================================================
// Kernel 3: softmax + weighted sum + LayerNorm, 2 warps/chunk,
//           fused sentence-max (atomicMax) + last-block decode
// grid = 2048 blocks, 128 threads (4 warps = 2 chunks/block)
// ============================================================
__global__ void __launch_bounds__(128)
chunk_embed_kernel(const float* __restrict__ tokens,
                   const float* __restrict__ ln_w,
                   const float* __restrict__ ln_b,
                   float* __restrict__ out_chunk,
                   float* __restrict__ out_sent) {
    int tid = threadIdx.x;
    int warp = tid >> 5;
    int lane = tid & 31;
    int bc = blockIdx.x * 2 + (warp >> 1);
    int half = warp & 1;
    int b = bc >> 7;
    int len = g_len[bc];
    int start = g_start[bc];
    float s0 = g_s0;

    float sc[LC];
    #pragma unroll
    for (int j = 0; j < LC; j++) {
        if (j < len) {
            int t = start + j;
            if (t > SEQ - 1) t = SEQ - 1;
            if (t < 0) t = 0;
            sc[j] = g_scores[b * SEQ + t];
        } else {
            sc[j] = s0;
        }
    }
    float m = sc[0];
    #pragma unroll
    for (int j = 1; j < LC; j++) m = fmaxf(m, sc[j]);
    float den = 0.0f;
    float w8[LC];
    #pragma unroll
    for (int j = 0; j < LC; j++) { w8[j] = expf(sc[j] - m); den += w8[j]; }
    float inv_den = 1.0f / den;

    float v[12];
    #pragma unroll
    for (int i = 0; i < 12; ++i) v[i] = 0.0f;
    int dbase = half * 384 + lane;
    #pragma unroll
    for (int j = 0; j < LC; j++) {
        if (j < len) {
            int t = start + j;
            if (t > SEQ - 1) t = SEQ - 1;
            if (t < 0) t = 0;
            float wj = w8[j] * inv_den;
            const float* row = tokens + ((size_t)b * SEQ + t) * HIDDEN + dbase;
            #pragma unroll
            for (int i = 0; i < 12; ++i)
                v[i] += wj * row[i * 32];
        }
    }

    __shared__ float ssum[4], ssq[4];
    float tot = 0.0f;
    #pragma unroll
    for (int i = 0; i < 12; ++i) tot += v[i];
    #pragma unroll
    for (int off = 16; off > 0; off >>= 1)
        tot += __shfl_xor_sync(0xffffffffu, tot, off);
    if (lane == 0) ssum[warp] = tot;
    __syncthreads();
    int wb = warp & ~1;
    float u = (ssum[wb] + ssum[wb + 1]) * (1.0f / HIDDEN);

    float sq = 0.0f;
    #pragma unroll
    for (int i = 0; i < 12; ++i) { v[i] -= u; sq += v[i] * v[i]; }
    #pragma unroll
    for (int off = 16; off > 0; off >>= 1)
        sq += __shfl_xor_sync(0xffffffffu, sq, off);
    if (lane == 0) ssq[warp] = sq;
    __syncthreads();
    float inv = rsqrtf((ssq[wb] + ssq[wb + 1]) * (1.0f / HIDDEN) + LN_EPS);

    float* outp = out_chunk + (size_t)bc * HIDDEN + dbase;
    unsigned int* mx = &g_maxu[b * HIDDEN + dbase];
    const float* lw = ln_w + dbase;
    const float* lb = ln_b + dbase;
    #pragma unroll
    for (int i = 0; i < 12; ++i) {
        float o = lw[i * 32] * (v[i] * inv) + lb[i * 32];
        outp[i * 32] = o;
        atomicMax(&mx[i * 32], fkey(o));
    }

    // completion: last block of this batch decodes the sentence max
    __threadfence();
    __syncthreads();
    __shared__ int sdone;
    if (tid == 0) {
        int c = atomicAdd(&g_cnt[b], 1);
        sdone = (c == 63);
    }
    __syncthreads();
    if (sdone) {
        __threadfence();
        #pragma unroll
        for (int i = 0; i < 6; ++i) {
            int d = tid + i * 128;
            out_sent[b * HIDDEN + d] = funkey(g_maxu[b * HIDDEN + d]);
        }
    }
}

// ============================================================
extern "C" void kernel_launch(void* const* d_in, const int* in_sizes, int n_in,
                              void* d_out, int out_size) {
    const float* tokens    = (const float*)d_in[0];
    const int*   chunk_lens= (const int*)d_in[1];
    const float* dense_w   = (const float*)d_in[2];
    const float* dense_b   = (const float*)d_in[3];
    const float* attn_bias = (const float*)d_in[4];
    const float* query     = (const float*)d_in[5];
    const float* ln_w      = (const float*)d_in[6];
    const float* ln_b      = (const float*)d_in[7];
    float* out = (float*)d_out;

    float* out_chunk = out;
    float* out_sent  = out + (size_t)BATCH * NCHUNK * HIDDEN;

    static bool attr_set = false;
    if (!attr_set) {
        cudaFuncSetAttribute(gemm_hmma_kernel,
                             cudaFuncAttributeMaxDynamicSharedMemorySize, SMEM_GEMM);
        attr_set = true;
    }

    setup_kernel<<<848, 256>>>(tokens, dense_w, chunk_lens, dense_b, attn_bias, query);

    dim3 gB(HIDDEN / BN, MAXT / BM, BATCH);   // (6, 6, 32), early exit on T_b
    gemm_hmma_kernel<<<gB, 256, SMEM_GEMM>>>(dense_b, attn_bias, query);

    chunk_embed_kernel<<<BATCH * NCHUNK / 2, 128>>>(tokens, ln_w, ln_b, out_chunk, out_sent);
}